// round 16
// baseline (speedup 1.0000x reference)
#include <cuda_runtime.h>
#include <math.h>
#include <stdint.h>

// ---------------- problem constants ----------------
#define HH 59
#define WWD 59
#define C_IN 2048
#define MIDC 512
#define NB 4
#define OHH 30
#define OWW 30
#define PPX 900
#define MP 3600
#define MMC 3481
#define HALF 29
#define NLOG 1770        // channels actually read per rh-group (30*59)
#define NLOGP 1792       // padded stride (14 * 128)

// ---------------- scratch ----------------
__device__ float g_xs [MP * C_IN];
__device__ float g_xcd[MP * 1024];
__device__ float g_z  [MP * 1024];
__device__ float g_yc [MP * MMC];        // reused as compact [30][120][1792]
__device__ float g_yd [MP * MMC];        // reused as compact [30][120][1792]
__device__ float g_Ac [NB * PPX * PPX];  // collect attention  [n][r][q]
__device__ float g_Ad [NB * PPX * PPX];  // distribute attention TRANSPOSED [n][q][r]
__device__ float g_agg[MP * 1024];
__device__ float g_xpt[C_IN * MP];
__device__ float g_s1[1024], g_t1[1024];
__device__ float g_s2[1024], g_t2[1024];
__device__ float g_s3[2048], g_t3[2048];
// tf32-rounded weight copies
__device__ float g_wrw [MIDC * C_IN];
__device__ float g_wrpw[MIDC * C_IN];
__device__ float g_wa1 [MIDC * MIDC];
__device__ float g_wap1[MIDC * MIDC];
__device__ float g_wa2 [MMC * MIDC];
__device__ float g_wap2[MMC * MIDC];
__device__ float g_wpj [C_IN * 1024];

__device__ __forceinline__ float tf32r(float x) {
    unsigned u;
    asm("cvt.rna.tf32.f32 %0, %1;" : "=r"(u) : "f"(x));
    return __uint_as_float(u);
}

// ---------------- BN fold ----------------
__device__ __forceinline__ void bnfold(const float* p, int C, int i, float* s, float* t) {
    float g = p[i], b = p[C + i], m = p[2 * C + i], v = p[3 * C + i];
    float sc = g * rsqrtf(v + 1e-5f);
    s[0] = sc; t[0] = b - m * sc;
}

__global__ void bnprep(const float* rbn, const float* rpbn, const float* abn,
                       const float* apbn, const float* pjbn) {
    int i = blockIdx.x * 256 + threadIdx.x;
    if (i < 512) {
        bnfold(rbn,  512, i, &g_s1[i],       &g_t1[i]);
        bnfold(rpbn, 512, i, &g_s1[512 + i], &g_t1[512 + i]);
        bnfold(abn,  512, i, &g_s2[i],       &g_t2[i]);
        bnfold(apbn, 512, i, &g_s2[512 + i], &g_t2[512 + i]);
    }
    if (i < 2048) bnfold(pjbn, 2048, i, &g_s3[i], &g_t3[i]);
}

__global__ void round_weights(const float* rw, const float* rpw, const float* a1w,
                              const float* ap1w, const float* a2w, const float* ap2w,
                              const float* pjw) {
    int seg = blockIdx.y;
    const float* s; float* d; int n;
    switch (seg) {
        case 0: s = rw;   d = g_wrw;  n = MIDC * C_IN; break;
        case 1: s = rpw;  d = g_wrpw; n = MIDC * C_IN; break;
        case 2: s = a1w;  d = g_wa1;  n = MIDC * MIDC; break;
        case 3: s = ap1w; d = g_wap1; n = MIDC * MIDC; break;
        case 4: s = a2w;  d = g_wa2;  n = MMC * MIDC;  break;
        case 5: s = ap2w; d = g_wap2; n = MMC * MIDC;  break;
        default: s = pjw; d = g_wpj;  n = C_IN * 1024; break;
    }
    for (int i = blockIdx.x * 256 + threadIdx.x; i < n; i += gridDim.x * 256)
        d[i] = tf32r(s[i]);
}

// ---------------- subsample + transpose (tf32-rounded) ----------------
__global__ void gather_sub(const float* __restrict__ x) {
    int nph = blockIdx.x;
    int n = nph / OHH, ph = nph % OHH;
    int c0 = blockIdx.y * 32;
    __shared__ float tile[32][31];
    int t = threadIdx.x;
    for (int e = t; e < 960; e += 256) {
        int cl = e / 30, pw = e % 30;
        tile[cl][pw] = x[((size_t)(n * C_IN + c0 + cl) * HH + 2 * ph) * WWD + 2 * pw];
    }
    __syncthreads();
    for (int e = t; e < 960; e += 256) {
        int pw = e / 32, cl = e % 32;
        g_xs[(size_t)(n * PPX + ph * OWW + pw) * C_IN + c0 + cl] = tf32r(tile[cl][pw]);
    }
}

// ---------------- TF32 GEMM (mma.sync), 512 threads, big tiles ----------------
// BM x BN in {256x128, 128x256}; 16 warps, warp tile 64x32; 3-stage cp.async.
#define STAGES 3
#define STG_FLOATS 13824                    // envelope: max (AFL+BFL) per stage
#define SMEM_BYTES (STAGES * STG_FLOATS * 4)

__device__ __forceinline__ void mma8(float* c, const unsigned* a, unsigned b0, unsigned b1) {
    asm volatile(
        "mma.sync.aligned.m16n8k8.row.col.f32.tf32.tf32.f32 "
        "{%0,%1,%2,%3}, {%4,%5,%6,%7}, {%8,%9}, {%0,%1,%2,%3};\n"
        : "+f"(c[0]), "+f"(c[1]), "+f"(c[2]), "+f"(c[3])
        : "r"(a[0]), "r"(a[1]), "r"(a[2]), "r"(a[3]), "r"(b0), "r"(b1));
}

__device__ __forceinline__ void cp16(float* dst, const float* src, bool pred) {
    uint32_t d = (uint32_t)__cvta_generic_to_shared(dst);
    asm volatile("cp.async.cg.shared.global [%0], [%1], 16, %2;\n"
                 :: "r"(d), "l"(src), "r"(pred ? 16 : 0));
}

// rows-major tile: R rows x 32 k, stride 36 (512 threads)
template <int R>
__device__ __forceinline__ void load_rk(float* S, const float* G, int ldg,
                                        int b0, int k0, int Rmax, int K, int tid) {
#pragma unroll
    for (int i = 0; i < R / 64; i++) {
        int fid = tid + i * 512;
        int row = fid >> 3, kq = (fid & 7) * 4;
        int gr = b0 + row, gk = k0 + kq;
        cp16(S + row * 36 + kq, G + (size_t)gr * ldg + gk, gr < Rmax && gk < K);
    }
}

// grouped A loader (logits): 128 rows, row i -> pixel (i/30)*900 + grp*30 + i%30
__device__ __forceinline__ void load_rk_grp(float* S, const float* G, int ldg,
                                            int k0, int K, int tid, int grp) {
#pragma unroll
    for (int i = 0; i < 2; i++) {
        int fid = tid + i * 512;
        int row = fid >> 3, kq = (fid & 7) * 4;
        int gr = (row / 30) * 900 + grp * 30 + (row % 30);
        int gk = k0 + kq;
        cp16(S + row * 36 + kq, G + (size_t)gr * ldg + gk, row < 120 && gk < K);
    }
}

// k-major tile: 32 k rows x CC cols, stride CC+8 (512 threads)
template <int CC>
__device__ __forceinline__ void load_kc(float* S, const float* G, int ldg,
                                        int b0, int k0, int Cmax, int K, int tid) {
    constexpr int QPR = CC / 4;
#pragma unroll
    for (int i = 0; i < CC / 64; i++) {
        int fid = tid + i * 512;
        int kr = fid / QPR, cq = (fid % QPR) * 4;
        int gk = k0 + kr, gc = b0 + cq;
        cp16(S + kr * (CC + 8) + cq, G + (size_t)gk * ldg + gc, gk < K && gc < Cmax);
    }
}

template <bool AT, bool BT, int BM, int BN>
__device__ __forceinline__ void compute_stage(const float* As, const float* Bs,
                                              float acc[4][4][4],
                                              int wm, int wn, int g8, int t4) {
#pragma unroll
    for (int kb = 0; kb < 32; kb += 8) {
        unsigned a[4][4];
#pragma unroll
        for (int fm = 0; fm < 4; fm++) {
            int m0 = wm * 64 + fm * 16;
            if (AT) {
                a[fm][0] = __float_as_uint(As[(kb + t4)     * (BM + 8) + m0 + g8]);
                a[fm][1] = __float_as_uint(As[(kb + t4)     * (BM + 8) + m0 + 8 + g8]);
                a[fm][2] = __float_as_uint(As[(kb + t4 + 4) * (BM + 8) + m0 + g8]);
                a[fm][3] = __float_as_uint(As[(kb + t4 + 4) * (BM + 8) + m0 + 8 + g8]);
            } else {
                a[fm][0] = __float_as_uint(As[(m0 + g8)     * 36 + kb + t4]);
                a[fm][1] = __float_as_uint(As[(m0 + 8 + g8) * 36 + kb + t4]);
                a[fm][2] = __float_as_uint(As[(m0 + g8)     * 36 + kb + t4 + 4]);
                a[fm][3] = __float_as_uint(As[(m0 + 8 + g8) * 36 + kb + t4 + 4]);
            }
        }
#pragma unroll
        for (int fn = 0; fn < 4; fn++) {
            int n0 = wn * 32 + fn * 8;
            unsigned b0, b1;
            if (BT) {
                b0 = __float_as_uint(Bs[(n0 + g8) * 36 + kb + t4]);
                b1 = __float_as_uint(Bs[(n0 + g8) * 36 + kb + t4 + 4]);
            } else {
                b0 = __float_as_uint(Bs[(kb + t4)     * (BN + 8) + n0 + g8]);
                b1 = __float_as_uint(Bs[(kb + t4 + 4) * (BN + 8) + n0 + g8]);
            }
#pragma unroll
            for (int fm = 0; fm < 4; fm++)
                mma8(acc[fm][fn], a[fm], b0, b1);
        }
    }
}

// EPI: 0 none, 1 relu(v*sc[col]+bi[col]), 2 relu(v*sc[row]+bi[row]); RND rounds output
// GRP: rh-grouped logits mode (A rows remapped, bm=0, C offset by grp*120*ldc)
template <int EPI, bool AT, bool BT, bool RND, bool GRP, int BM, int BN>
__device__ __forceinline__ void tgemm_core(
    const float* __restrict__ A, int lda,
    const float* __restrict__ B, int ldb,
    float* __restrict__ C, int ldc,
    int M, int N, int K,
    const float* __restrict__ sc, const float* __restrict__ bi)
{
    constexpr int AFL = AT ? 32 * (BM + 8) : BM * 36;   // floats per A stage
    constexpr int BFL = BT ? BN * 36 : 32 * (BN + 8);   // floats per B stage
    constexpr int MW = BM / 64;                          // m-warps (4 or 2)
    extern __shared__ float sm[];
    float* As = sm;
    float* Bs = sm + STAGES * AFL;
    int tid = threadIdx.x;
    int lane = tid & 31, wid = tid >> 5;
    int wm = wid & (MW - 1), wn = wid / MW;
    int grp = blockIdx.y;
    int bm = GRP ? 0 : grp * BM;
    int bn = blockIdx.x * BN;
    int g8 = lane >> 2, t4 = lane & 3;
    if (GRP) C += (size_t)grp * 120 * ldc;

    float acc[4][4][4];
#pragma unroll
    for (int i = 0; i < 4; i++)
#pragma unroll
        for (int j = 0; j < 4; j++)
#pragma unroll
            for (int q = 0; q < 4; q++) acc[i][j][q] = 0.f;

    int KT = (K + 31) / 32;

#define LOAD_STAGE(Sidx, Koff) do {                                              \
        if (GRP)      load_rk_grp(As + (Sidx) * AFL, A, lda, (Koff), K, tid, grp); \
        else if (AT)  load_kc<BM>(As + (Sidx) * AFL, A, lda, bm, (Koff), M, K, tid); \
        else          load_rk<BM>(As + (Sidx) * AFL, A, lda, bm, (Koff), M, K, tid); \
        if (BT) load_rk<BN>(Bs + (Sidx) * BFL, B, ldb, bn, (Koff), N, K, tid);   \
        else    load_kc<BN>(Bs + (Sidx) * BFL, B, ldb, bn, (Koff), N, K, tid);   \
    } while (0)

    LOAD_STAGE(0, 0);
    asm volatile("cp.async.commit_group;\n");
    if (KT > 1) LOAD_STAGE(1, 32);
    asm volatile("cp.async.commit_group;\n");

    for (int kt = 0; kt < KT; kt++) {
        if (kt + 2 < KT) {
            int s = (kt + 2) % STAGES;
            LOAD_STAGE(s, (kt + 2) * 32);
        }
        asm volatile("cp.async.commit_group;\n");
        asm volatile("cp.async.wait_group 2;\n");
        __syncthreads();
        int s = kt % STAGES;
        compute_stage<AT && !GRP, BT, BM, BN>(As + s * AFL, Bs + s * BFL, acc, wm, wn, g8, t4);
        __syncthreads();
    }
#undef LOAD_STAGE

#pragma unroll
    for (int fm = 0; fm < 4; fm++) {
#pragma unroll
        for (int fn = 0; fn < 4; fn++) {
            int gm0 = bm + wm * 64 + fm * 16 + g8;
            int gn0 = bn + wn * 32 + fn * 8 + 2 * t4;
#pragma unroll
            for (int h = 0; h < 2; h++) {
                int gm = gm0 + h * 8;
                if (gm >= M) continue;
#pragma unroll
                for (int q = 0; q < 2; q++) {
                    int gn = gn0 + q;
                    if (gn >= N) continue;
                    float v = acc[fm][fn][h * 2 + q];
                    if (EPI == 1) v = fmaxf(fmaf(v, sc[gn], bi[gn]), 0.f);
                    if (EPI == 2) v = fmaxf(fmaf(v, sc[gm], bi[gm]), 0.f);
                    if (RND) v = tf32r(v);
                    C[(size_t)gm * ldc + gn] = v;
                }
            }
        }
    }
}

template <int EPI, bool BT, bool RND>
__global__ void __launch_bounds__(512) tgemm_dual(
    const float* A0, const float* A1, int lda,
    const float* B0, const float* B1, int ldb,
    float* C0, float* C1, int ldc,
    int M, int N, int K,
    const float* sc0, const float* sc1,
    const float* bi0, const float* bi1)
{
    int z = blockIdx.z;
    tgemm_core<EPI, false, BT, RND, false, 256, 128>(
        z ? A1 : A0, lda, z ? B1 : B0, ldb, z ? C1 : C0, ldc,
        M, N, K, z ? sc1 : sc0, z ? bi1 : bi0);
}

// rh-grouped logits: grid (7, 30, 2); tile 128(M=120) x 256; compact output [30][120][1792]
__global__ void __launch_bounds__(512) tgemm_logits() {
    int zb = blockIdx.z;
    int grp = blockIdx.y;
    const float* A = g_z + (zb ? 512 : 0);
    const float* W = zb ? g_wap2 : g_wa2;
    const float* B = W + (size_t)(HALF - grp) * 59 * MIDC;
    float* C = zb ? g_yd : g_yc;
    tgemm_core<0, false, true, false, true, 128, 256>(
        A, 1024, B, MIDC, C, NLOGP, 120, NLOG, MIDC, nullptr, nullptr);
}

// Batched attention aggregation: z = br*4 + n; tile 256x128
__global__ void __launch_bounds__(512) tgemm_agg() {
    int zb = blockIdx.z;
    int n = zb & 3, br = zb >> 2;
    const float* B = g_xcd + (size_t)n * PPX * 1024 + br * 512;
    float* C = g_agg + (size_t)n * PPX * 1024 + br * 512;
    if (br == 0) {
        const float* A = g_Ac + (size_t)n * PPX * PPX;
        tgemm_core<0, false, false, true, false, 256, 128>(A, PPX, B, 1024, C, 1024,
                                                           PPX, MIDC, PPX, nullptr, nullptr);
    } else {
        const float* A = g_Ad + (size_t)n * PPX * PPX;   // [q][r]
        tgemm_core<0, true, false, true, false, 256, 128>(A, PPX, B, 1024, C, 1024,
                                                          PPX, MIDC, PPX, nullptr, nullptr);
    }
}

// ---------------- psa_mask gather + softmax ----------------
// collect from compact yc: pixel (n, rh, rw) -> row (rh*120 + n*30 + rw);
// channel for q=(qh,qw): lc = qh*59 + (qw-rw+29)
__global__ void softmax_collect(float* __restrict__ Ao) {
    int nr = blockIdx.x;
    int n = nr / PPX, r = nr % PPX;
    int rh = r / OWW, rw = r % OWW;
    const float* row = g_yc + (size_t)(rh * 120 + n * 30 + rw) * NLOGP;
    __shared__ float buf[PPX];
    __shared__ float red[256];
    int t = threadIdx.x;
    float mx = -1e30f;
    for (int q = t; q < PPX; q += 256) {
        int qh = q / OWW, qw = q % OWW;
        float v = row[qh * 59 + (qw - rw + HALF)];
        buf[q] = v;
        mx = fmaxf(mx, v);
    }
    red[t] = mx; __syncthreads();
    for (int s = 128; s > 0; s >>= 1) { if (t < s) red[t] = fmaxf(red[t], red[t + s]); __syncthreads(); }
    mx = red[0]; __syncthreads();
    float sum = 0.f;
    for (int q = t; q < PPX; q += 256) {
        float e = __expf(buf[q] - mx);
        buf[q] = e; sum += e;
    }
    red[t] = sum; __syncthreads();
    for (int s = 128; s > 0; s >>= 1) { if (t < s) red[t] += red[t + s]; __syncthreads(); }
    float inv = 1.f / red[0];
    float* out = Ao + (size_t)nr * PPX;
    for (int q = t; q < PPX; q += 256) out[q] = tf32r(buf[q] * inv);
}

// fused distribute softmax: 2-pass gathered read from compact yd; writes Ad[n][q][r].
__global__ void softmax_dist_fused() {
    int n = blockIdx.y;
    int rr = threadIdx.x & 63, ql = threadIdx.x >> 6;
    int r = blockIdx.x * 64 + rr;
    bool ok = r < PPX;
    int rh = r / OWW, rw = r % OWW;
    __shared__ float smx[4][64];
    __shared__ float ssm[4][64];
    float m = -1e30f, s = 0.f;
    if (ok) {
        for (int q = ql; q < PPX; q += 4) {
            int qh = q / OWW, qw = q % OWW;
            float v = g_yd[(size_t)(qh * 120 + n * 30 + qw) * NLOGP + rh * 59 + (rw - qw + HALF)];
            if (v > m) { s *= __expf(m - v); m = v; }
            s += __expf(v - m);
        }
    }
    smx[ql][rr] = m; ssm[ql][rr] = s;
    __syncthreads();
    if (ql == 0) {
        float M0 = fmaxf(fmaxf(smx[0][rr], smx[1][rr]), fmaxf(smx[2][rr], smx[3][rr]));
        float S = ssm[0][rr] * __expf(smx[0][rr] - M0)
                + ssm[1][rr] * __expf(smx[1][rr] - M0)
                + ssm[2][rr] * __expf(smx[2][rr] - M0)
                + ssm[3][rr] * __expf(smx[3][rr] - M0);
        smx[0][rr] = M0;
        ssm[0][rr] = 1.f / S;
    }
    __syncthreads();
    float M0 = smx[0][rr], inv = ssm[0][rr];
    float* o = g_Ad + (size_t)n * PPX * PPX;
    if (ok) {
        for (int q = ql; q < PPX; q += 4) {
            int qh = q / OWW, qw = q % OWW;
            float v = g_yd[(size_t)(qh * 120 + n * 30 + qw) * NLOGP + rh * 59 + (rw - qw + HALF)];
            o[(size_t)q * PPX + r] = tf32r(__expf(v - M0) * inv);
        }
    }
}

// ---------------- output assembly ----------------
__global__ void upsample(float* __restrict__ out) {
    int b = blockIdx.x;
    int n = b >> 11, c = b & 2047;
    __shared__ float src[PPX];
    const float* g = g_xpt + (size_t)c * MP + n * PPX;
    int t = threadIdx.x;
    for (int p = t; p < PPX; p += 256) src[p] = g[p];
    __syncthreads();
    float* orow = out + ((size_t)(n * 4096 + 2048 + c)) * MMC;
    for (int s = t; s < MMC; s += 256) {
        int i = s / 59, j = s % 59;
        int i0 = min(i >> 1, OHH - 2);
        int j0 = min(j >> 1, OWW - 2);
        float fh = i * 0.5f - i0, fw = j * 0.5f - j0;
        float v00 = src[i0 * OWW + j0],       v01 = src[i0 * OWW + j0 + 1];
        float v10 = src[(i0 + 1) * OWW + j0], v11 = src[(i0 + 1) * OWW + j0 + 1];
        orow[s] = (1.f - fh) * ((1.f - fw) * v00 + fw * v01)
                + fh * ((1.f - fw) * v10 + fw * v11);
    }
}

// ---------------- launch ----------------
extern "C" void kernel_launch(void* const* d_in, const int* in_sizes, int n_in,
                              void* d_out, int out_size) {
    const float* x    = (const float*)d_in[0];
    const float* rw   = (const float*)d_in[1];
    const float* rbn  = (const float*)d_in[2];
    const float* a1w  = (const float*)d_in[3];
    const float* abn  = (const float*)d_in[4];
    const float* a2w  = (const float*)d_in[5];
    const float* rpw  = (const float*)d_in[6];
    const float* rpbn = (const float*)d_in[7];
    const float* ap1w = (const float*)d_in[8];
    const float* apbn = (const float*)d_in[9];
    const float* ap2w = (const float*)d_in[10];
    const float* pjw  = (const float*)d_in[11];
    const float* pjbn = (const float*)d_in[12];
    float* out = (float*)d_out;

    float *xs, *xcd, *z, *agg, *Ac, *xpt;
    float *s1, *t1, *s2, *t2, *s3, *t3;
    float *wrw, *wrpw, *wa1, *wap1, *wpj;
    cudaGetSymbolAddress((void**)&xs,  g_xs);
    cudaGetSymbolAddress((void**)&xcd, g_xcd);
    cudaGetSymbolAddress((void**)&z,   g_z);
    cudaGetSymbolAddress((void**)&agg, g_agg);
    cudaGetSymbolAddress((void**)&xpt, g_xpt);
    cudaGetSymbolAddress((void**)&Ac,  g_Ac);
    cudaGetSymbolAddress((void**)&s1,  g_s1);
    cudaGetSymbolAddress((void**)&t1,  g_t1);
    cudaGetSymbolAddress((void**)&s2,  g_s2);
    cudaGetSymbolAddress((void**)&t2,  g_t2);
    cudaGetSymbolAddress((void**)&s3,  g_s3);
    cudaGetSymbolAddress((void**)&t3,  g_t3);
    cudaGetSymbolAddress((void**)&wrw,  g_wrw);
    cudaGetSymbolAddress((void**)&wrpw, g_wrpw);
    cudaGetSymbolAddress((void**)&wa1,  g_wa1);
    cudaGetSymbolAddress((void**)&wap1, g_wap1);
    cudaGetSymbolAddress((void**)&wpj,  g_wpj);

    cudaFuncSetAttribute(tgemm_dual<1, true, true>,  cudaFuncAttributeMaxDynamicSharedMemorySize, SMEM_BYTES);
    cudaFuncSetAttribute(tgemm_logits,               cudaFuncAttributeMaxDynamicSharedMemorySize, SMEM_BYTES);
    cudaFuncSetAttribute(tgemm_dual<2, true, false>, cudaFuncAttributeMaxDynamicSharedMemorySize, SMEM_BYTES);
    cudaFuncSetAttribute(tgemm_agg,                  cudaFuncAttributeMaxDynamicSharedMemorySize, SMEM_BYTES);

    // 0. BN fold + weight rounding
    bnprep<<<8, 256>>>(rbn, rpbn, abn, apbn, pjbn);
    round_weights<<<dim3(512, 7), 256>>>(rw, rpw, a1w, ap1w, a2w, ap2w, pjw);

    // 1. subsample+transpose input
    gather_sub<<<dim3(NB * OHH, C_IN / 32), 256>>>(x);

    // 2. conv1 both branches (z=2): M=3600, N=512, K=2048, tile 256x128
    {
        dim3 g(MIDC / 128, (MP + 255) / 256, 2);
        tgemm_dual<1, true, true><<<g, 512, SMEM_BYTES>>>(
            xs, xs, C_IN, wrw, wrpw, C_IN, xcd, xcd + 512, 1024,
            MP, MIDC, C_IN, s1, s1 + 512, t1, t1 + 512);
    }

    // 3. attention conv1 both branches (z=2): M=3600, N=512, K=512
    {
        dim3 g(MIDC / 128, (MP + 255) / 256, 2);
        tgemm_dual<1, true, true><<<g, 512, SMEM_BYTES>>>(
            xcd, xcd + 512, 1024, wa1, wap1, MIDC, z, z + 512, 1024,
            MP, MIDC, MIDC, s2, s2 + 512, t2, t2 + 512);
    }

    // 4. logits, rh-grouped: 30 x (120 x 1770 x 512), tile 128x256
    tgemm_logits<<<dim3(NLOGP / 256, 30, 2), 512, SMEM_BYTES>>>();

    // 5. softmaxes
    softmax_collect<<<MP, 256>>>(Ac);
    softmax_dist_fused<<<dim3(15, NB), 256>>>();

    // 6. aggregation (batched over n x branch): M=900, N=512, K=900, tile 256x128
    {
        dim3 g(MIDC / 128, (PPX + 255) / 256, 8);
        tgemm_agg<<<g, 512, SMEM_BYTES>>>();
    }

    // 7. projection: M=2048, N=3600, K=1024, tile 256x128
    {
        dim3 g((MP + 127) / 128, C_IN / 256, 1);
        tgemm_dual<2, true, false><<<g, 512, SMEM_BYTES>>>(
            wpj, wpj, 1024, agg, agg, 1024, xpt, xpt, MP,
            C_IN, MP, 1024, s3, s3, t3, t3);
    }

    // 8. assemble output: channels 0..2047 via D2D memcpy (contiguous per batch)
    for (int n = 0; n < NB; n++) {
        cudaMemcpyAsync(out + (size_t)n * 4096 * MMC,
                        x   + (size_t)n * C_IN * MMC,
                        (size_t)C_IN * MMC * sizeof(float),
                        cudaMemcpyDeviceToDevice);
    }
    // channels 2048..4095: bilinear upsample
    upsample<<<NB * C_IN, 256>>>(out);
}

// round 17
// speedup vs baseline: 1.2921x; 1.2921x over previous
#include <cuda_runtime.h>
#include <cuda_fp16.h>
#include <math.h>
#include <stdint.h>

// ---------------- problem constants ----------------
#define HH 59
#define WWD 59
#define C_IN 2048
#define MIDC 512
#define NB 4
#define OHH 30
#define OWW 30
#define PPX 900
#define MP 3600
#define MMC 3481
#define HALF 29
#define NLOG 1770
#define NLOGP 1792

// ---------------- scratch ----------------
__device__ __half g_xs_h [MP * C_IN];
__device__ __half g_xcd_h[MP * 1024];     // conv1 out (att1 A)
__device__ float  g_xcd  [MP * 1024];     // fp32 copy (agg B)
__device__ __half g_z_h  [MP * 1024];
__device__ float  g_yc [MP * MMC];        // compact [30][120][1792]
__device__ float  g_yd [MP * MMC];
__device__ float  g_Ac [NB * PPX * PPX];  // collect attention [n][r][q]
__device__ float  g_Ad [NB * PPX * PPX];  // distribute attention [n][q][r]
__device__ __half g_agg_h[MP * 1024];
__device__ float  g_xpt[C_IN * MP];
__device__ float g_s1[1024], g_t1[1024];
__device__ float g_s2[1024], g_t2[1024];
__device__ float g_s3[2048], g_t3[2048];
// half weights
__device__ __half g_wrw_h [MIDC * C_IN];
__device__ __half g_wrpw_h[MIDC * C_IN];
__device__ __half g_wa1_h [MIDC * MIDC];
__device__ __half g_wap1_h[MIDC * MIDC];
__device__ __half g_wa2_h [MMC * MIDC];
__device__ __half g_wap2_h[MMC * MIDC];
__device__ __half g_wpj_h [C_IN * 1024];

__device__ __forceinline__ float tf32r(float x) {
    unsigned u;
    asm("cvt.rna.tf32.f32 %0, %1;" : "=r"(u) : "f"(x));
    return __uint_as_float(u);
}

// ---------------- BN fold ----------------
__device__ __forceinline__ void bnfold(const float* p, int C, int i, float* s, float* t) {
    float g = p[i], b = p[C + i], m = p[2 * C + i], v = p[3 * C + i];
    float sc = g * rsqrtf(v + 1e-5f);
    s[0] = sc; t[0] = b - m * sc;
}

__global__ void bnprep(const float* rbn, const float* rpbn, const float* abn,
                       const float* apbn, const float* pjbn) {
    int i = blockIdx.x * 256 + threadIdx.x;
    if (i < 512) {
        bnfold(rbn,  512, i, &g_s1[i],       &g_t1[i]);
        bnfold(rpbn, 512, i, &g_s1[512 + i], &g_t1[512 + i]);
        bnfold(abn,  512, i, &g_s2[i],       &g_t2[i]);
        bnfold(apbn, 512, i, &g_s2[512 + i], &g_t2[512 + i]);
    }
    if (i < 2048) bnfold(pjbn, 2048, i, &g_s3[i], &g_t3[i]);
}

__global__ void round_weights(const float* rw, const float* rpw, const float* a1w,
                              const float* ap1w, const float* a2w, const float* ap2w,
                              const float* pjw) {
    int seg = blockIdx.y;
    const float* s; __half* d; int n;
    switch (seg) {
        case 0: s = rw;   d = g_wrw_h;  n = MIDC * C_IN; break;
        case 1: s = rpw;  d = g_wrpw_h; n = MIDC * C_IN; break;
        case 2: s = a1w;  d = g_wa1_h;  n = MIDC * MIDC; break;
        case 3: s = ap1w; d = g_wap1_h; n = MIDC * MIDC; break;
        case 4: s = a2w;  d = g_wa2_h;  n = MMC * MIDC;  break;
        case 5: s = ap2w; d = g_wap2_h; n = MMC * MIDC;  break;
        default: s = pjw; d = g_wpj_h;  n = C_IN * 1024; break;
    }
    for (int i = blockIdx.x * 256 + threadIdx.x; i < n; i += gridDim.x * 256)
        d[i] = __float2half(s[i]);
}

// ---------------- subsample + transpose -> half ----------------
__global__ void gather_sub(const float* __restrict__ x) {
    int nph = blockIdx.x;
    int n = nph / OHH, ph = nph % OHH;
    int c0 = blockIdx.y * 32;
    __shared__ float tile[32][31];
    int t = threadIdx.x;
    for (int e = t; e < 960; e += 256) {
        int cl = e / 30, pw = e % 30;
        tile[cl][pw] = x[((size_t)(n * C_IN + c0 + cl) * HH + 2 * ph) * WWD + 2 * pw];
    }
    __syncthreads();
    for (int e = t; e < 960; e += 256) {
        int pw = e / 32, cl = e % 32;
        g_xs_h[(size_t)(n * PPX + ph * OWW + pw) * C_IN + c0 + cl] = __float2half(tile[cl][pw]);
    }
}

// half -> float copy for agg B
__global__ void h2f_xcd() {
    for (size_t i = (size_t)blockIdx.x * 256 + threadIdx.x; i < (size_t)MP * 1024;
         i += (size_t)gridDim.x * 256)
        g_xcd[i] = __half2float(g_xcd_h[i]);
}

// ---------------- common cp.async ----------------
__device__ __forceinline__ void cp16(void* dst, const void* src, bool pred) {
    uint32_t d = (uint32_t)__cvta_generic_to_shared(dst);
    asm volatile("cp.async.cg.shared.global [%0], [%1], 16, %2;\n"
                 :: "r"(d), "l"(src), "r"(pred ? 16 : 0));
}

// ============================================================
// FP16 NT GEMM: mma.sync.m16n8k16, tile 128x128, 256 thr, 3 stages
// smem: [row][k] halves, stride 40 (u32-stride 20) -> conflict-free
// ============================================================
#define HSTRIDE 40
#define HAFL (128 * HSTRIDE)               // halves per stage (A or B)
#define HSMEM_BYTES (3 * 2 * HAFL * 2)     // 61440 B

__device__ __forceinline__ void mma16(float* c, const unsigned* a, unsigned b0, unsigned b1) {
    asm volatile(
        "mma.sync.aligned.m16n8k16.row.col.f32.f16.f16.f32 "
        "{%0,%1,%2,%3}, {%4,%5,%6,%7}, {%8,%9}, {%0,%1,%2,%3};\n"
        : "+f"(c[0]), "+f"(c[1]), "+f"(c[2]), "+f"(c[3])
        : "r"(a[0]), "r"(a[1]), "r"(a[2]), "r"(a[3]), "r"(b0), "r"(b1));
}

// rows-major half tile: 128 rows x 32 k halves (64 B/row -> 4 chunks)
__device__ __forceinline__ void hload_rk(__half* S, const __half* G, int ldg,
                                         int b0, int k0, int Rmax, int K, int tid) {
#pragma unroll
    for (int i = 0; i < 2; i++) {
        int fid = tid + i * 256;
        int row = fid >> 2, kq = (fid & 3) * 8;
        int gr = b0 + row, gk = k0 + kq;
        cp16(S + row * HSTRIDE + kq, G + (size_t)gr * ldg + gk, gr < Rmax && gk < K);
    }
}

// grouped A loader (logits): row i -> pixel (i/30)*900 + grp*30 + i%30 (M=120)
__device__ __forceinline__ void hload_rk_grp(__half* S, const __half* G, int ldg,
                                             int k0, int K, int tid, int grp) {
#pragma unroll
    for (int i = 0; i < 2; i++) {
        int fid = tid + i * 256;
        int row = fid >> 2, kq = (fid & 3) * 8;
        int gr = (row / 30) * 900 + grp * 30 + (row % 30);
        int gk = k0 + kq;
        cp16(S + row * HSTRIDE + kq, G + (size_t)gr * ldg + gk, row < 120 && gk < K);
    }
}

__device__ __forceinline__ void hcompute_stage(const __half* As, const __half* Bs,
                                               float acc[4][4][4],
                                               int wm, int wn, int g8, int t4) {
    const unsigned* A32 = (const unsigned*)As;
    const unsigned* B32 = (const unsigned*)Bs;
#pragma unroll
    for (int kb = 0; kb < 2; kb++) {           // two k16 steps per 32-k stage
        int kk = kb * 8;                        // u32 offset (16 halves)
        unsigned a[4][4];
#pragma unroll
        for (int fm = 0; fm < 4; fm++) {
            int m0 = wm * 64 + fm * 16;
            a[fm][0] = A32[(m0 + g8)     * 20 + kk + t4];
            a[fm][1] = A32[(m0 + 8 + g8) * 20 + kk + t4];
            a[fm][2] = A32[(m0 + g8)     * 20 + kk + t4 + 4];
            a[fm][3] = A32[(m0 + 8 + g8) * 20 + kk + t4 + 4];
        }
#pragma unroll
        for (int fn = 0; fn < 4; fn++) {
            int n0 = wn * 32 + fn * 8;
            unsigned b0 = B32[(n0 + g8) * 20 + kk + t4];
            unsigned b1 = B32[(n0 + g8) * 20 + kk + t4 + 4];
#pragma unroll
            for (int fm = 0; fm < 4; fm++)
                mma16(acc[fm][fn], a[fm], b0, b1);
        }
    }
}

// EPI: 0 none, 1 relu(v*sc[col]+bi[col]), 2 relu(v*sc[row]+bi[row])
// OUTF: write float C; else half C.  GRP: rh-grouped logits A remap.
template <int EPI, bool GRP, bool OUTF>
__device__ __forceinline__ void hgemm_core(
    const __half* __restrict__ A, int lda,
    const __half* __restrict__ B, int ldb,
    void* __restrict__ Cv, int ldc,
    int M, int N, int K,
    const float* __restrict__ sc, const float* __restrict__ bi)
{
    extern __shared__ __half hsm[];
    __half* As = hsm;
    __half* Bs = hsm + 3 * HAFL;
    int tid = threadIdx.x;
    int lane = tid & 31, wid = tid >> 5;
    int wm = wid & 1, wn = wid >> 1;
    int grp = blockIdx.y;
    int bm = GRP ? 0 : grp * 128;
    int bn = blockIdx.x * 128;
    int g8 = lane >> 2, t4 = lane & 3;
    float* Cf = (float*)Cv;
    __half* Ch = (__half*)Cv;
    size_t coff = GRP ? (size_t)grp * 120 * ldc : 0;

    float acc[4][4][4];
#pragma unroll
    for (int i = 0; i < 4; i++)
#pragma unroll
        for (int j = 0; j < 4; j++)
#pragma unroll
            for (int q = 0; q < 4; q++) acc[i][j][q] = 0.f;

    int KT = (K + 31) / 32;

#define HLOAD(Sidx, Koff) do {                                                   \
        if (GRP) hload_rk_grp(As + (Sidx) * HAFL, A, lda, (Koff), K, tid, grp);  \
        else     hload_rk(As + (Sidx) * HAFL, A, lda, bm, (Koff), M, K, tid);    \
        hload_rk(Bs + (Sidx) * HAFL, B, ldb, bn, (Koff), N, K, tid);             \
    } while (0)

    HLOAD(0, 0);
    asm volatile("cp.async.commit_group;\n");
    if (KT > 1) HLOAD(1, 32);
    asm volatile("cp.async.commit_group;\n");

    for (int kt = 0; kt < KT; kt++) {
        if (kt + 2 < KT) HLOAD((kt + 2) % 3, (kt + 2) * 32);
        asm volatile("cp.async.commit_group;\n");
        asm volatile("cp.async.wait_group 2;\n");
        __syncthreads();
        int s = kt % 3;
        hcompute_stage(As + s * HAFL, Bs + s * HAFL, acc, wm, wn, g8, t4);
        __syncthreads();
    }
#undef HLOAD

#pragma unroll
    for (int fm = 0; fm < 4; fm++) {
#pragma unroll
        for (int fn = 0; fn < 4; fn++) {
            int gm0 = bm + wm * 64 + fm * 16 + g8;
            int gn0 = bn + wn * 32 + fn * 8 + 2 * t4;
#pragma unroll
            for (int h = 0; h < 2; h++) {
                int gm = gm0 + h * 8;
                if (gm >= M) continue;
#pragma unroll
                for (int q = 0; q < 2; q++) {
                    int gn = gn0 + q;
                    if (gn >= N) continue;
                    float v = acc[fm][fn][h * 2 + q];
                    if (EPI == 1) v = fmaxf(fmaf(v, sc[gn], bi[gn]), 0.f);
                    if (EPI == 2) v = fmaxf(fmaf(v, sc[gm], bi[gm]), 0.f);
                    if (OUTF) Cf[coff + (size_t)gm * ldc + gn] = v;
                    else      Ch[coff + (size_t)gm * ldc + gn] = __float2half(v);
                }
            }
        }
    }
}

template <int EPI, bool OUTF>
__global__ void __launch_bounds__(256, 2) hgemm_dual(
    const __half* A0, const __half* A1, int lda,
    const __half* B0, const __half* B1, int ldb,
    void* C0, void* C1, int ldc,
    int M, int N, int K,
    const float* sc0, const float* sc1, const float* bi0, const float* bi1)
{
    int z = blockIdx.z;
    hgemm_core<EPI, false, OUTF>(z ? A1 : A0, lda, z ? B1 : B0, ldb, z ? C1 : C0, ldc,
                                 M, N, K, z ? sc1 : sc0, z ? bi1 : bi0);
}

// rh-grouped logits: grid (14, 30, 2); float out, compact [30][120][1792]
__global__ void __launch_bounds__(256, 2) hgemm_logits() {
    int zb = blockIdx.z;
    int grp = blockIdx.y;
    const __half* A = g_z_h + (zb ? 512 : 0);
    const __half* W = zb ? g_wap2_h : g_wa2_h;
    const __half* B = W + (size_t)(HALF - grp) * 59 * MIDC;
    float* C = zb ? g_yd : g_yc;
    hgemm_core<0, true, true>(A, 1024, B, MIDC, C, NLOGP, 120, NLOG, MIDC, nullptr, nullptr);
}

// ============================================================
// FP32/TF32 GEMM core (aggregation only) — unchanged from R14 except half output
// ============================================================
#define ASZ 4608
#define BSZ 4608
#define SMEM_BYTES (3 * (ASZ + BSZ) * 4)

__device__ __forceinline__ void mma8(float* c, const unsigned* a, unsigned b0, unsigned b1) {
    asm volatile(
        "mma.sync.aligned.m16n8k8.row.col.f32.tf32.tf32.f32 "
        "{%0,%1,%2,%3}, {%4,%5,%6,%7}, {%8,%9}, {%0,%1,%2,%3};\n"
        : "+f"(c[0]), "+f"(c[1]), "+f"(c[2]), "+f"(c[3])
        : "r"(a[0]), "r"(a[1]), "r"(a[2]), "r"(a[3]), "r"(b0), "r"(b1));
}

__device__ __forceinline__ void load_rk(float* S, const float* G, int ldg,
                                        int b0, int k0, int R, int K, int tid) {
#pragma unroll
    for (int i = 0; i < 4; i++) {
        int fid = tid + i * 256;
        int row = fid >> 3, kq = (fid & 7) * 4;
        int gr = b0 + row, gk = k0 + kq;
        cp16(S + row * 36 + kq, G + (size_t)gr * ldg + gk, gr < R && gk < K);
    }
}

__device__ __forceinline__ void load_kc(float* S, const float* G, int ldg,
                                        int b0, int k0, int Ncols, int K, int tid) {
#pragma unroll
    for (int i = 0; i < 4; i++) {
        int fid = tid + i * 256;
        int kr = fid >> 5, cq = (fid & 31) * 4;
        int gk = k0 + kr, gc = b0 + cq;
        cp16(S + kr * 136 + cq, G + (size_t)gk * ldg + gc, gk < K && gc < Ncols);
    }
}

template <bool AT>
__device__ __forceinline__ void compute_stage(const float* As, const float* Bs,
                                              float acc[4][4][4],
                                              int wm, int wn, int g8, int t4) {
#pragma unroll
    for (int kb = 0; kb < 32; kb += 8) {
        unsigned a[4][4];
#pragma unroll
        for (int fm = 0; fm < 4; fm++) {
            int m0 = wm * 64 + fm * 16;
            if (AT) {
                a[fm][0] = __float_as_uint(As[(kb + t4)     * 136 + m0 + g8]);
                a[fm][1] = __float_as_uint(As[(kb + t4)     * 136 + m0 + 8 + g8]);
                a[fm][2] = __float_as_uint(As[(kb + t4 + 4) * 136 + m0 + g8]);
                a[fm][3] = __float_as_uint(As[(kb + t4 + 4) * 136 + m0 + 8 + g8]);
            } else {
                a[fm][0] = __float_as_uint(As[(m0 + g8)     * 36 + kb + t4]);
                a[fm][1] = __float_as_uint(As[(m0 + 8 + g8) * 36 + kb + t4]);
                a[fm][2] = __float_as_uint(As[(m0 + g8)     * 36 + kb + t4 + 4]);
                a[fm][3] = __float_as_uint(As[(m0 + 8 + g8) * 36 + kb + t4 + 4]);
            }
        }
#pragma unroll
        for (int fn = 0; fn < 4; fn++) {
            int n0 = wn * 32 + fn * 8;
            unsigned b0 = __float_as_uint(Bs[(kb + t4)     * 136 + n0 + g8]);
            unsigned b1 = __float_as_uint(Bs[(kb + t4 + 4) * 136 + n0 + g8]);
#pragma unroll
            for (int fm = 0; fm < 4; fm++)
                mma8(acc[fm][fn], a[fm], b0, b1);
        }
    }
}

// agg core: A float ([m][k] or AT [k][m]), B float NN [k][n]; half output
template <bool AT>
__device__ __forceinline__ void tgemm_core_agg(
    const float* __restrict__ A, int lda,
    const float* __restrict__ B, int ldb,
    __half* __restrict__ C, int ldc,
    int M, int N, int K)
{
    extern __shared__ float sm[];
    float* As = sm;
    float* Bs = sm + 3 * ASZ;
    int tid = threadIdx.x;
    int lane = tid & 31, wid = tid >> 5;
    int wm = wid & 1, wn = wid >> 1;
    int bm = blockIdx.y * 128, bn = blockIdx.x * 128;
    int g8 = lane >> 2, t4 = lane & 3;

    float acc[4][4][4];
#pragma unroll
    for (int i = 0; i < 4; i++)
#pragma unroll
        for (int j = 0; j < 4; j++)
#pragma unroll
            for (int q = 0; q < 4; q++) acc[i][j][q] = 0.f;

    int KT = (K + 31) / 32;

#define TLOAD(Sidx, Koff) do {                                             \
        if (AT) load_kc(As + (Sidx) * ASZ, A, lda, bm, (Koff), M, K, tid); \
        else    load_rk(As + (Sidx) * ASZ, A, lda, bm, (Koff), M, K, tid); \
        load_kc(Bs + (Sidx) * BSZ, B, ldb, bn, (Koff), N, K, tid);         \
    } while (0)

    TLOAD(0, 0);
    asm volatile("cp.async.commit_group;\n");
    if (KT > 1) TLOAD(1, 32);
    asm volatile("cp.async.commit_group;\n");

    for (int kt = 0; kt < KT; kt++) {
        if (kt + 2 < KT) TLOAD((kt + 2) % 3, (kt + 2) * 32);
        asm volatile("cp.async.commit_group;\n");
        asm volatile("cp.async.wait_group 2;\n");
        __syncthreads();
        int s = kt % 3;
        compute_stage<AT>(As + s * ASZ, Bs + s * BSZ, acc, wm, wn, g8, t4);
        __syncthreads();
    }
#undef TLOAD

#pragma unroll
    for (int fm = 0; fm < 4; fm++) {
#pragma unroll
        for (int fn = 0; fn < 4; fn++) {
            int gm0 = bm + wm * 64 + fm * 16 + g8;
            int gn0 = bn + wn * 32 + fn * 8 + 2 * t4;
#pragma unroll
            for (int h = 0; h < 2; h++) {
                int gm = gm0 + h * 8;
                if (gm >= M) continue;
#pragma unroll
                for (int q = 0; q < 2; q++) {
                    int gn = gn0 + q;
                    if (gn >= N) continue;
                    C[(size_t)gm * ldc + gn] = __float2half(acc[fm][fn][h * 2 + q]);
                }
            }
        }
    }
}

__global__ void __launch_bounds__(256, 2) tgemm_agg() {
    int zb = blockIdx.z;
    int n = zb & 3, br = zb >> 2;
    const float* B = g_xcd + (size_t)n * PPX * 1024 + br * 512;
    __half* C = g_agg_h + (size_t)n * PPX * 1024 + br * 512;
    if (br == 0) {
        const float* A = g_Ac + (size_t)n * PPX * PPX;
        tgemm_core_agg<false>(A, PPX, B, 1024, C, 1024, PPX, MIDC, PPX);
    } else {
        const float* A = g_Ad + (size_t)n * PPX * PPX;   // [q][r]
        tgemm_core_agg<true>(A, PPX, B, 1024, C, 1024, PPX, MIDC, PPX);
    }
}

// ---------------- psa_mask gather + softmax ----------------
__global__ void softmax_collect(float* __restrict__ Ao) {
    int nr = blockIdx.x;
    int n = nr / PPX, r = nr % PPX;
    int rh = r / OWW, rw = r % OWW;
    const float* row = g_yc + (size_t)(rh * 120 + n * 30 + rw) * NLOGP;
    __shared__ float buf[PPX];
    __shared__ float red[256];
    int t = threadIdx.x;
    float mx = -1e30f;
    for (int q = t; q < PPX; q += 256) {
        int qh = q / OWW, qw = q % OWW;
        float v = row[qh * 59 + (qw - rw + HALF)];
        buf[q] = v;
        mx = fmaxf(mx, v);
    }
    red[t] = mx; __syncthreads();
    for (int s = 128; s > 0; s >>= 1) { if (t < s) red[t] = fmaxf(red[t], red[t + s]); __syncthreads(); }
    mx = red[0]; __syncthreads();
    float sum = 0.f;
    for (int q = t; q < PPX; q += 256) {
        float e = __expf(buf[q] - mx);
        buf[q] = e; sum += e;
    }
    red[t] = sum; __syncthreads();
    for (int s = 128; s > 0; s >>= 1) { if (t < s) red[t] += red[t + s]; __syncthreads(); }
    float inv = 1.f / red[0];
    float* out = Ao + (size_t)nr * PPX;
    for (int q = t; q < PPX; q += 256) out[q] = tf32r(buf[q] * inv);
}

__global__ void softmax_dist_fused() {
    int n = blockIdx.y;
    int rr = threadIdx.x & 63, ql = threadIdx.x >> 6;
    int r = blockIdx.x * 64 + rr;
    bool ok = r < PPX;
    int rh = r / OWW, rw = r % OWW;
    __shared__ float smx[4][64];
    __shared__ float ssm[4][64];
    float m = -1e30f, s = 0.f;
    if (ok) {
        for (int q = ql; q < PPX; q += 4) {
            int qh = q / OWW, qw = q % OWW;
            float v = g_yd[(size_t)(qh * 120 + n * 30 + qw) * NLOGP + rh * 59 + (rw - qw + HALF)];
            if (v > m) { s *= __expf(m - v); m = v; }
            s += __expf(v - m);
        }
    }
    smx[ql][rr] = m; ssm[ql][rr] = s;
    __syncthreads();
    if (ql == 0) {
        float M0 = fmaxf(fmaxf(smx[0][rr], smx[1][rr]), fmaxf(smx[2][rr], smx[3][rr]));
        float S = ssm[0][rr] * __expf(smx[0][rr] - M0)
                + ssm[1][rr] * __expf(smx[1][rr] - M0)
                + ssm[2][rr] * __expf(smx[2][rr] - M0)
                + ssm[3][rr] * __expf(smx[3][rr] - M0);
        smx[0][rr] = M0;
        ssm[0][rr] = 1.f / S;
    }
    __syncthreads();
    float M0 = smx[0][rr], inv = ssm[0][rr];
    float* o = g_Ad + (size_t)n * PPX * PPX;
    if (ok) {
        for (int q = ql; q < PPX; q += 4) {
            int qh = q / OWW, qw = q % OWW;
            float v = g_yd[(size_t)(qh * 120 + n * 30 + qw) * NLOGP + rh * 59 + (rw - qw + HALF)];
            o[(size_t)q * PPX + r] = tf32r(__expf(v - M0) * inv);
        }
    }
}

// ---------------- output assembly ----------------
__global__ void upsample(float* __restrict__ out) {
    int b = blockIdx.x;
    int n = b >> 11, c = b & 2047;
    __shared__ float src[PPX];
    const float* g = g_xpt + (size_t)c * MP + n * PPX;
    int t = threadIdx.x;
    for (int p = t; p < PPX; p += 256) src[p] = g[p];
    __syncthreads();
    float* orow = out + ((size_t)(n * 4096 + 2048 + c)) * MMC;
    for (int s = t; s < MMC; s += 256) {
        int i = s / 59, j = s % 59;
        int i0 = min(i >> 1, OHH - 2);
        int j0 = min(j >> 1, OWW - 2);
        float fh = i * 0.5f - i0, fw = j * 0.5f - j0;
        float v00 = src[i0 * OWW + j0],       v01 = src[i0 * OWW + j0 + 1];
        float v10 = src[(i0 + 1) * OWW + j0], v11 = src[(i0 + 1) * OWW + j0 + 1];
        orow[s] = (1.f - fh) * ((1.f - fw) * v00 + fw * v01)
                + fh * ((1.f - fw) * v10 + fw * v11);
    }
}

// ---------------- launch ----------------
extern "C" void kernel_launch(void* const* d_in, const int* in_sizes, int n_in,
                              void* d_out, int out_size) {
    const float* x    = (const float*)d_in[0];
    const float* rw   = (const float*)d_in[1];
    const float* rbn  = (const float*)d_in[2];
    const float* a1w  = (const float*)d_in[3];
    const float* abn  = (const float*)d_in[4];
    const float* a2w  = (const float*)d_in[5];
    const float* rpw  = (const float*)d_in[6];
    const float* rpbn = (const float*)d_in[7];
    const float* ap1w = (const float*)d_in[8];
    const float* apbn = (const float*)d_in[9];
    const float* ap2w = (const float*)d_in[10];
    const float* pjw  = (const float*)d_in[11];
    const float* pjbn = (const float*)d_in[12];
    float* out = (float*)d_out;

    __half *xs_h, *xcd_h, *z_h, *agg_h;
    __half *wrw_h, *wrpw_h, *wa1_h, *wap1_h, *wpj_h;
    float *Ac, *xpt;
    float *s1, *t1, *s2, *t2, *s3, *t3;
    cudaGetSymbolAddress((void**)&xs_h,  g_xs_h);
    cudaGetSymbolAddress((void**)&xcd_h, g_xcd_h);
    cudaGetSymbolAddress((void**)&z_h,   g_z_h);
    cudaGetSymbolAddress((void**)&agg_h, g_agg_h);
    cudaGetSymbolAddress((void**)&xpt,   g_xpt);
    cudaGetSymbolAddress((void**)&Ac,    g_Ac);
    cudaGetSymbolAddress((void**)&s1,  g_s1);
    cudaGetSymbolAddress((void**)&t1,  g_t1);
    cudaGetSymbolAddress((void**)&s2,  g_s2);
    cudaGetSymbolAddress((void**)&t2,  g_t2);
    cudaGetSymbolAddress((void**)&s3,  g_s3);
    cudaGetSymbolAddress((void**)&t3,  g_t3);
    cudaGetSymbolAddress((void**)&wrw_h,  g_wrw_h);
    cudaGetSymbolAddress((void**)&wrpw_h, g_wrpw_h);
    cudaGetSymbolAddress((void**)&wa1_h,  g_wa1_h);
    cudaGetSymbolAddress((void**)&wap1_h, g_wap1_h);
    cudaGetSymbolAddress((void**)&wpj_h,  g_wpj_h);

    cudaFuncSetAttribute(hgemm_dual<1, false>, cudaFuncAttributeMaxDynamicSharedMemorySize, HSMEM_BYTES);
    cudaFuncSetAttribute(hgemm_dual<2, true>,  cudaFuncAttributeMaxDynamicSharedMemorySize, HSMEM_BYTES);
    cudaFuncSetAttribute(hgemm_logits,         cudaFuncAttributeMaxDynamicSharedMemorySize, HSMEM_BYTES);
    cudaFuncSetAttribute(tgemm_agg,            cudaFuncAttributeMaxDynamicSharedMemorySize, SMEM_BYTES);

    // 0. BN fold + weight conversion
    bnprep<<<8, 256>>>(rbn, rpbn, abn, apbn, pjbn);
    round_weights<<<dim3(512, 7), 256>>>(rw, rpw, a1w, ap1w, a2w, ap2w, pjw);

    // 1. subsample+transpose input -> half
    gather_sub<<<dim3(NB * OHH, C_IN / 32), 256>>>(x);

    // 2. conv1 both branches (z=2): M=3600, N=512, K=2048; half out
    {
        dim3 g(MIDC / 128, (MP + 127) / 128, 2);
        hgemm_dual<1, false><<<g, 256, HSMEM_BYTES>>>(
            xs_h, xs_h, C_IN, wrw_h, wrpw_h, C_IN, xcd_h, xcd_h + 512, 1024,
            MP, MIDC, C_IN, s1, s1 + 512, t1, t1 + 512);
    }
    // float copy for agg B
    h2f_xcd<<<2048, 256>>>();

    // 3. attention conv1 both branches (z=2): M=3600, N=512, K=512; half out
    {
        dim3 g(MIDC / 128, (MP + 127) / 128, 2);
        hgemm_dual<1, false><<<g, 256, HSMEM_BYTES>>>(
            xcd_h, xcd_h + 512, 1024, wa1_h, wap1_h, MIDC, z_h, z_h + 512, 1024,
            MP, MIDC, MIDC, s2, s2 + 512, t2, t2 + 512);
    }

    // 4. logits, rh-grouped: 30 x (120 x 1770 x 512); float out
    hgemm_logits<<<dim3(NLOGP / 128, 30, 2), 256, HSMEM_BYTES>>>();

    // 5. softmaxes
    softmax_collect<<<MP, 256>>>(Ac);
    softmax_dist_fused<<<dim3(15, NB), 256>>>();

    // 6. aggregation (tf32, half out): M=900, N=512, K=900
    {
        dim3 g(MIDC / 128, (PPX + 127) / 128, 8);
        tgemm_agg<<<g, 256, SMEM_BYTES>>>();
    }

    // 7. projection (fp16): M=2048, N=3600, K=1024; float out
    {
        dim3 g((MP + 127) / 128, C_IN / 128, 1);
        hgemm_dual<2, true><<<g, 256, HSMEM_BYTES>>>(
            wpj_h, wpj_h, 1024, agg_h, agg_h, 1024, xpt, xpt, MP,
            C_IN, MP, 1024, s3, s3, t3, t3);
    }

    // 8. assemble output
    for (int n = 0; n < NB; n++) {
        cudaMemcpyAsync(out + (size_t)n * 4096 * MMC,
                        x   + (size_t)n * C_IN * MMC,
                        (size_t)C_IN * MMC * sizeof(float),
                        cudaMemcpyDeviceToDevice);
    }
    upsample<<<NB * C_IN, 256>>>(out);
}